// round 10
// baseline (speedup 1.0000x reference)
#include <cuda_runtime.h>

#define F       4096
#define TSTEPS  2048
#define ODIM    512

// Persistent kernel partitioning: 147 CTAs x 28 rows (last CTA overlaps by
// duplicate-writing identical values -- benign).
#define NB      147
#define NR      28
#define R1      9             // rows pinned in registers (144 regs)
#define R2      14            // rows pinned in shared memory (224 KB)
#define RG      (NR - R1 - R2) // 5 rows streamed from L2

#define NTHREADS 256
#define NWARPS   8
#define SMEM_BYTES ((R2 * F + NWARPS * 32) * sizeof(float))

__device__ float        g_feats[TSTEPS + 1][F];   // row 0 stays zero (initial state)
// Per-CTA arrival flags, each on its own 128B line. Monotonic across replays.
__device__ unsigned int g_flag[NB * 32];
// Epoch broadcast, 8 padded copies (CTA b polls copy b&7). Monotonic.
__device__ unsigned int g_epoch[8 * 32];

__device__ __forceinline__ void ffma2(unsigned long long& acc,
                                      unsigned long long a, unsigned long long b) {
    asm("fma.rn.f32x2 %0, %1, %2, %0;" : "+l"(acc) : "l"(a), "l"(b));
}
__device__ __forceinline__ float hadd2(unsigned long long a) {
    float x, y;
    asm("mov.b64 {%0, %1}, %2;" : "=f"(x), "=f"(y) : "l"(a));
    return x + y;
}
__device__ __forceinline__ void st_release(unsigned int* p, unsigned int v) {
    asm volatile("st.global.release.gpu.u32 [%0], %1;" :: "l"(p), "r"(v) : "memory");
}
__device__ __forceinline__ unsigned int ld_acquire(const unsigned int* p) {
    unsigned int v;
    asm volatile("ld.global.acquire.gpu.u32 %0, [%1];" : "=r"(v) : "l"(p) : "memory");
    return v;
}

// Readout GEMM tile constants (epilogue)
#define TO 64
#define TT 64
#define TK 32
#define NTILES ((ODIM / TO) * (TSTEPS / TT))   // 8 * 32 = 256

__global__ void __launch_bounds__(NTHREADS, 1)
rc_persistent_kernel(const float* __restrict__ x,
                     const float* __restrict__ W,
                     const float* __restrict__ wout,
                     float* __restrict__ out)
{
    extern __shared__ float smem[];
    float* sW  = smem;               // [R2][F]
    float* red = smem + R2 * F;      // [NWARPS][32]

    const int tid  = threadIdx.x;
    const int lane = tid & 31;
    const int warp = tid >> 5;
    const int b    = blockIdx.x;
    const int rstart = (b * NR > F - NR) ? (F - NR) : (b * NR);

    // Monotonic bases (all flags/epochs are equal at launch start).
    const unsigned int fbase = *(volatile unsigned int*)&g_flag[b * 32];

    // This lane owns 16 columns: c0 + j*128, j = 0..3 (one float4 each).
    const int c0 = warp * 512 + lane * 4;

    // --- Pin R1 rows of W in registers (as packed f32x2 pairs) ---
    unsigned long long wrf[R1][8];
    #pragma unroll
    for (int r = 0; r < R1; ++r) {
        #pragma unroll
        for (int j = 0; j < 4; ++j) {
            ulonglong2 wv = *(const ulonglong2*)(W + (size_t)(rstart + r) * F + c0 + j * 128);
            wrf[r][2 * j]     = wv.x;
            wrf[r][2 * j + 1] = wv.y;
        }
    }
    // --- Pin R2 rows of W in SMEM ---
    {
        const float4* src = (const float4*)(W + (size_t)(rstart + R1) * F);
        float4*       dst = (float4*)sW;
        for (int i = tid; i < R2 * (F / 4); i += NTHREADS) dst[i] = src[i];
    }
    __syncthreads();

    for (int t = 0; t < TSTEPS; ++t) {
        // Prefetch this step's x value for the row this thread finalizes.
        float xv = 0.0f;
        if (tid < NR) xv = x[(size_t)(rstart + tid) * TSTEPS + t];

        // Load f^{(t)} for this lane's 16 columns (packed pairs).
        unsigned long long fp[8];
        #pragma unroll
        for (int j = 0; j < 4; ++j) {
            ulonglong2 fv = *(const ulonglong2*)(g_feats[t] + c0 + j * 128);
            fp[2 * j]     = fv.x;
            fp[2 * j + 1] = fv.y;
        }

        float v[32];
        #pragma unroll
        for (int i = 0; i < 32; ++i) v[i] = 0.0f;

        // Register-resident rows
        #pragma unroll
        for (int r = 0; r < R1; ++r) {
            unsigned long long acc = 0ull;
            #pragma unroll
            for (int j = 0; j < 8; ++j) ffma2(acc, wrf[r][j], fp[j]);
            v[r] = hadd2(acc);
        }
        // SMEM-resident rows
        #pragma unroll
        for (int r = 0; r < R2; ++r) {
            unsigned long long acc = 0ull;
            #pragma unroll
            for (int j = 0; j < 4; ++j) {
                ulonglong2 wv = *(const ulonglong2*)(sW + r * F + c0 + j * 128);
                ffma2(acc, wv.x, fp[2 * j]);
                ffma2(acc, wv.y, fp[2 * j + 1]);
            }
            v[R1 + r] = hadd2(acc);
        }
        // L2-streamed rows
        #pragma unroll
        for (int r = 0; r < RG; ++r) {
            unsigned long long acc = 0ull;
            const float* wrow = W + (size_t)(rstart + R1 + R2 + r) * F + c0;
            #pragma unroll
            for (int j = 0; j < 4; ++j) {
                ulonglong2 wv = *(const ulonglong2*)(wrow + j * 128);
                ffma2(acc, wv.x, fp[2 * j]);
                ffma2(acc, wv.y, fp[2 * j + 1]);
            }
            v[R1 + R2 + r] = hadd2(acc);
        }

        // Butterfly reduce-scatter: lane l ends with this warp's total for row l.
        #pragma unroll
        for (int d = 16; d >= 1; d >>= 1) {
            const bool up = (lane & d) != 0;
            #pragma unroll
            for (int i = 0; i < d; ++i) {
                float mine   = up ? v[i + d] : v[i];
                float theirs = up ? v[i]     : v[i + d];
                float recv = __shfl_xor_sync(0xffffffffu, theirs, d);
                v[i] = mine + recv;
            }
        }
        red[warp * 32 + lane] = v[0];
        __syncthreads();

        if (tid < NR) {
            float s = red[tid];
            #pragma unroll
            for (int w = 1; w < NWARPS; ++w) s += red[w * 32 + tid];
            s += xv;
            s = fminf(1.0f, fmaxf(-1.0f, s));
            g_feats[t + 1][rstart + tid] = s;
        }

        // ---- Two-level grid barrier (aggregator = CTA 0) ----
        const unsigned int target = fbase + (unsigned)(t + 1);
        __syncthreads();   // feats STGs happen-before tid0's release store
        if (tid == 0) st_release(&g_flag[b * 32], target);

        if (b == 0) {
            // Aggregate: threads 0..146 each watch one CTA flag.
            if (tid < NB) {
                while ((int)(ld_acquire(&g_flag[tid * 32]) - target) < 0) { }
            }
            __syncthreads();
            // Publish epoch to 8 broadcast lines.
            if (tid < 8) st_release(&g_epoch[tid * 32], target);
        } else {
            if (tid == 0) {
                while ((int)(ld_acquire(&g_epoch[(b & 7) * 32]) - target) < 0) { }
            }
            __syncthreads();
        }
    }

    // =====================================================================
    // Epilogue: readout GEMM  out[o, t] = sum_k wout[o, k] * feats[t+1][k]
    // 256 tiles of 64x64, distributed across the 147 persistent CTAs.
    // =====================================================================
    __syncthreads();
    float* sw  = smem;                       // [TK][TO+4]
    float* sfe = smem + TK * (TO + 4);       // [TK][TT+4]

    const int lk = tid & 31;
    const int lr = tid >> 5;
    const int to = (tid & 15) * 4;
    const int tt = (tid >> 4) * 4;

    for (int tile = b; tile < NTILES; tile += NB) {
        const int o0 = (tile >> 5) * TO;          // 8 o-tiles
        const int t0 = (tile & 31) * TT;          // 32 t-tiles

        float acc[4][4] = {};

        for (int k0 = 0; k0 < F; k0 += TK) {
            #pragma unroll
            for (int i = 0; i < 8; ++i) {
                const int o = lr * 8 + i;
                sw[lk * (TO + 4) + o] = wout[(size_t)(o0 + o) * F + k0 + lk];
            }
            #pragma unroll
            for (int i = 0; i < 8; ++i) {
                const int tr = lr * 8 + i;
                sfe[lk * (TT + 4) + tr] = g_feats[t0 + tr + 1][k0 + lk];
            }
            __syncthreads();

            #pragma unroll
            for (int k = 0; k < TK; ++k) {
                const float4 rw = *(const float4*)&sw [k * (TO + 4) + to];
                const float4 rf = *(const float4*)&sfe[k * (TT + 4) + tt];
                acc[0][0] = fmaf(rw.x, rf.x, acc[0][0]);
                acc[0][1] = fmaf(rw.x, rf.y, acc[0][1]);
                acc[0][2] = fmaf(rw.x, rf.z, acc[0][2]);
                acc[0][3] = fmaf(rw.x, rf.w, acc[0][3]);
                acc[1][0] = fmaf(rw.y, rf.x, acc[1][0]);
                acc[1][1] = fmaf(rw.y, rf.y, acc[1][1]);
                acc[1][2] = fmaf(rw.y, rf.z, acc[1][2]);
                acc[1][3] = fmaf(rw.y, rf.w, acc[1][3]);
                acc[2][0] = fmaf(rw.z, rf.x, acc[2][0]);
                acc[2][1] = fmaf(rw.z, rf.y, acc[2][1]);
                acc[2][2] = fmaf(rw.z, rf.z, acc[2][2]);
                acc[2][3] = fmaf(rw.z, rf.w, acc[2][3]);
                acc[3][0] = fmaf(rw.w, rf.x, acc[3][0]);
                acc[3][1] = fmaf(rw.w, rf.y, acc[3][1]);
                acc[3][2] = fmaf(rw.w, rf.z, acc[3][2]);
                acc[3][3] = fmaf(rw.w, rf.w, acc[3][3]);
            }
            __syncthreads();
        }

        #pragma unroll
        for (int i = 0; i < 4; ++i)
            #pragma unroll
            for (int j = 0; j < 4; ++j)
                out[(size_t)(o0 + to + i) * TSTEPS + t0 + tt + j] = acc[i][j];
    }
}

extern "C" void kernel_launch(void* const* d_in, const int* in_sizes, int n_in,
                              void* d_out, int out_size)
{
    const float* x    = (const float*)d_in[0];   // [F, T]
    const float* W    = (const float*)d_in[1];   // [F, F]
    const float* wout = (const float*)d_in[2];   // [O, F]
    float* out = (float*)d_out;                  // [O, T]

    cudaFuncSetAttribute(rc_persistent_kernel,
                         cudaFuncAttributeMaxDynamicSharedMemorySize,
                         (int)SMEM_BYTES);

    rc_persistent_kernel<<<NB, NTHREADS, SMEM_BYTES>>>(x, W, wout, out);
}